// round 17
// baseline (speedup 1.0000x reference)
#include <cuda_runtime.h>
#include <cuda_bf16.h>
#include <cstdint>

#define B_    128
#define T_    1024
#define RNN_  1024
#define EMB_  512
#define ATT_  128
#define NF_   32
#define KS_   31
#define PAD_  15

#define NPROD_ 512
#define NCONS_ 128
#define NTHR_  640

// energies GEMM per 128-t tile: D[128,128] = A[t,192] * B[192,a], B dedup to 128 rows
#define LDAB_  136                              // bf16 elems per smem row (272 B)
#define OFF_B_    (128 * LDAB_ * 2)             // 34816
#define OFF_AWR_  (OFF_B_ + 128 * LDAB_ * 2)    // 69632: aw rows 2 x 1056 f
#define OFF_V_    (OFF_AWR_ + 8448)             // 78080
#define OFF_E_    (OFF_V_ + 512)                // 78592: energies 4 x 1024 f (also pq scratch)
#define OFF_HID_  (OFF_E_ + 16384)              // 94976: hidden row 1024 f
#define OFF_EC_   (OFF_HID_ + 4096)             // 99072: combined energies 1024 f
#define OFF_P_    (OFF_EC_ + 4096)              // 103168: tile p 128 f
#define OFF_CRED_ (OFF_P_ + 512)                // 103680: consumer reduce 8 f
#define OFF_FLAG_ (OFF_CRED_ + 32)              // 103712
#define ESMEM_    (OFF_FLAG_ + 16)              // 103728

// scratch inside the (not yet built) A region during staging:
#define SCR_WLOC_  0          // 4096 f = 16384 B
#define SCR_WCONV_ 16384      // 1984 f = 7936 B (ends at 24320 < 34816)

#define BAR_PROD() asm volatile("bar.sync 1, 512;" ::: "memory")
#define BAR_CONS() asm volatile("bar.sync 2, 128;" ::: "memory")

// ---------------- helpers ----------------
__device__ __forceinline__ float tanh_fast(float x) {
    float y; asm("tanh.approx.f32 %0, %1;" : "=f"(y) : "f"(x)); return y;
}
__device__ __forceinline__ uint32_t smem_u32(const void* p) {
    uint32_t a;
    asm("{ .reg .u64 t; cvta.to.shared.u64 t, %1; cvt.u32.u64 %0, t; }" : "=r"(a) : "l"(p));
    return a;
}
__device__ __forceinline__ void ldsm_x4(uint32_t* r, uint32_t addr) {
    asm volatile("ldmatrix.sync.aligned.m8n8.x4.shared.b16 {%0,%1,%2,%3}, [%4];"
                 : "=r"(r[0]), "=r"(r[1]), "=r"(r[2]), "=r"(r[3]) : "r"(addr));
}
__device__ __forceinline__ void ldsm_x2t(uint32_t& b0, uint32_t& b1, uint32_t addr) {
    asm volatile("ldmatrix.sync.aligned.m8n8.x2.trans.shared.b16 {%0,%1}, [%2];"
                 : "=r"(b0), "=r"(b1) : "r"(addr));
}
__device__ __forceinline__ void mma_bf16(float* d, const uint32_t* a, uint32_t b0, uint32_t b1) {
    asm volatile("mma.sync.aligned.m16n8k16.row.col.f32.bf16.bf16.f32 "
                 "{%0,%1,%2,%3}, {%4,%5,%6,%7}, {%8,%9}, {%0,%1,%2,%3};"
                 : "+f"(d[0]), "+f"(d[1]), "+f"(d[2]), "+f"(d[3])
                 : "r"(a[0]), "r"(a[1]), "r"(a[2]), "r"(a[3]), "r"(b0), "r"(b1));
}

// ====== fused kernel: producer warps (MMA energies) + consumer warps (online ctx) ======
__global__ __launch_bounds__(NTHR_, 1) void fused_kernel(
    const float* __restrict__ aw,      // [B,2,T]
    const float* __restrict__ pmem,    // [B,T,ATT]
    const float* __restrict__ vvec,    // [ATT]
    const unsigned char* __restrict__ mask,
    const float* __restrict__ hidden,  // [B,RNN]
    const float* __restrict__ wq,      // [RNN,ATT]
    const float* __restrict__ wconv,   // [NF,62]
    const float* __restrict__ wloc,    // [NF,ATT]
    const float* __restrict__ memory,  // [B,T,EMB]
    float* __restrict__ out)           // [B*EMB ctx | B*T weights]
{
    extern __shared__ __align__(16) char sm[];
    const uint32_t sbase = smem_u32(sm);

    const int b   = blockIdx.x;
    const int tid = threadIdx.x;
    const float NINF = -__int_as_float(0x7f800000);

    float* s_e  = (float*)(sm + OFF_E_);      // [4][1024]; pq scratch early
    volatile int* s_flag = (volatile int*)(sm + OFF_FLAG_);

    if (tid == 0) *s_flag = 0;
    __syncthreads();   // only full-block barrier; roles diverge after

    if (tid < NPROD_) {
        // ================= PRODUCER (warps 0-15) =================
        const int wm = tid >> 5, lane = tid & 31;
        const int sg = wm >> 2;          // 0..3: t rows [32*sg, 32*sg+32)
        const int nq = wm & 3;           // 0..3: cols [32nq, 32nq+32)

        float* s_awr = (float*)(sm + OFF_AWR_);
        float* s_v   = (float*)(sm + OFF_V_);
        float* s_hid = (float*)(sm + OFF_HID_);
        __nv_bfloat16* sB = (__nv_bfloat16*)(sm + OFF_B_);

        // ---------- staging ----------
        for (int idx = tid; idx < 2112; idx += NPROD_) {
            int ch = idx / 1056, i = idx - ch * 1056;
            int gt = i - 16;
            s_awr[idx] = (gt >= 0 && gt < T_) ? aw[((size_t)b * 2 + ch) * T_ + gt] : 0.f;
        }
        if (tid < 128) s_v[tid] = vvec[tid];
        s_hid[tid]       = hidden[(size_t)b * RNN_ + tid];
        s_hid[tid + 512] = hidden[(size_t)b * RNN_ + tid + 512];
        {
            float* s_wloc  = (float*)(sm + SCR_WLOC_);
            float* s_wconv = (float*)(sm + SCR_WCONV_);
            #pragma unroll
            for (int i = 0; i < 8; ++i) s_wloc[tid + 512 * i] = wloc[tid + 512 * i];
            for (int m = tid; m < NF_ * 62; m += NPROD_) s_wconv[m] = wconv[m];
        }
        BAR_PROD();

        // ---------- phase A: pq partials + W2 -> B rows ----------
        {
            const int kq = tid >> 5, a4 = tid & 31;
            const float4* wq4 = (const float4*)wq + (size_t)(kq * 64) * (ATT_ / 4) + a4;
            const float*  hp  = s_hid + kq * 64;
            float4 acc0 = make_float4(0.f, 0.f, 0.f, 0.f);
            float4 acc1 = make_float4(0.f, 0.f, 0.f, 0.f);
            #pragma unroll 8
            for (int k = 0; k < 64; k += 2) {
                float h0 = hp[k], h1 = hp[k + 1];
                float4 w0 = wq4[(size_t)k * (ATT_ / 4)];
                float4 w1 = wq4[(size_t)(k + 1) * (ATT_ / 4)];
                acc0.x = fmaf(h0, w0.x, acc0.x);
                acc0.y = fmaf(h0, w0.y, acc0.y);
                acc0.z = fmaf(h0, w0.z, acc0.z);
                acc0.w = fmaf(h0, w0.w, acc0.w);
                acc1.x = fmaf(h1, w1.x, acc1.x);
                acc1.y = fmaf(h1, w1.y, acc1.y);
                acc1.z = fmaf(h1, w1.z, acc1.z);
                acc1.w = fmaf(h1, w1.w, acc1.w);
            }
            acc0.x += acc1.x; acc0.y += acc1.y; acc0.z += acc1.z; acc0.w += acc1.w;
            ((float4*)s_e)[kq * 32 + a4] = acc0;

            const float* s_wloc  = (const float*)(sm + SCR_WLOC_);
            const float* s_wconv = (const float*)(sm + SCR_WCONV_);
            for (int m = tid; m < 62 * 128; m += NPROD_) {
                int j = m >> 7, a = m & 127;
                float acc = 0.f;
                #pragma unroll 8
                for (int f = 0; f < NF_; ++f)
                    acc = fmaf(s_wconv[f * 62 + j], s_wloc[f * ATT_ + a], acc);
                __nv_bfloat16 hi = __float2bfloat16_rn(acc);
                sB[j * LDAB_ + a]        = hi;
                sB[(64 + j) * LDAB_ + a] = __float2bfloat16_rn(acc - __bfloat162float(hi));
            }
            if (tid < 128) {
                sB[ 63 * LDAB_ + tid] = __float2bfloat16_rn(0.f);
                sB[127 * LDAB_ + tid] = __float2bfloat16_rn(0.f);
            }
        }
        BAR_PROD();

        // ---------- phase B: pq reduce -> B rows 62/126; const A cols ----------
        if (tid < 32) {
            float4 r = ((const float4*)s_e)[tid];
            #pragma unroll
            for (int q = 1; q < 16; ++q) {
                float4 v = ((const float4*)s_e)[q * 32 + tid];
                r.x += v.x; r.y += v.y; r.z += v.z; r.w += v.w;
            }
            float vals[4] = {r.x, r.y, r.z, r.w};
            #pragma unroll
            for (int c = 0; c < 4; ++c) {
                int col = 4 * tid + c;
                __nv_bfloat16 hi = __float2bfloat16_rn(vals[c]);
                sB[ 62 * LDAB_ + col] = hi;
                sB[126 * LDAB_ + col] = __float2bfloat16_rn(vals[c] - __bfloat162float(hi));
            }
        }
        if (tid < 128) {
            __nv_bfloat16* arow = (__nv_bfloat16*)(sm + tid * (LDAB_ * 2));
            arow[62]  = __float2bfloat16_rn(1.f);
            arow[63]  = __float2bfloat16_rn(0.f);
            arow[126] = __float2bfloat16_rn(0.f);
            arow[127] = __float2bfloat16_rn(0.f);
        }

        const uint32_t aAddr0 = sbase + (32 * sg + (lane & 15)) * (LDAB_ * 2) + (lane >> 4) * 16;
        const uint32_t aAddr1 = aAddr0 + 16 * (LDAB_ * 2);
        const uint32_t bAddrQ = sbase + OFF_B_ + (lane & 15) * (LDAB_ * 2) + nq * 64;
        const int rowL = tid >> 2;
        const int jq   = tid & 3;

        // ---------- 8 t-tiles ----------
        for (int it = 0; it < 8; ++it) {
            const int t0g = it * 128;

            BAR_PROD();
            {
                __nv_bfloat16* arow = (__nv_bfloat16*)(sm + rowL * (LDAB_ * 2));
                const int base0 = 1 + t0g + rowL;
                #pragma unroll
                for (int q = 0; q < 16; ++q) {
                    int j = jq * 16 + q;
                    if (j < 62) {
                        float x = (j < 31) ? s_awr[base0 + j] : s_awr[1056 + base0 + (j - 31)];
                        __nv_bfloat16 hi = __float2bfloat16_rn(x);
                        arow[j]      = hi;
                        arow[64 + j] = __float2bfloat16_rn(x - __bfloat162float(hi));
                    }
                }
            }
            BAR_PROD();

            float acc0[4][4], acc1[4][4];
            uint32_t afc0[4][4], afc1[4][4];
            #pragma unroll
            for (int n = 0; n < 4; ++n) {
                acc0[n][0] = 0.f; acc0[n][1] = 0.f; acc0[n][2] = 0.f; acc0[n][3] = 0.f;
                acc1[n][0] = 0.f; acc1[n][1] = 0.f; acc1[n][2] = 0.f; acc1[n][3] = 0.f;
            }
            #pragma unroll
            for (int s = 0; s < 12; ++s) {
                uint32_t afr0[4], afr1[4];
                const uint32_t* a0;
                const uint32_t* a1;
                if (s < 4) {
                    ldsm_x4(afc0[s], aAddr0 + s * 32);
                    ldsm_x4(afc1[s], aAddr1 + s * 32);
                    a0 = afc0[s]; a1 = afc1[s];
                } else if (s < 8) {
                    ldsm_x4(afr0, aAddr0 + s * 32);
                    ldsm_x4(afr1, aAddr1 + s * 32);
                    a0 = afr0; a1 = afr1;
                } else {
                    a0 = afc0[s - 8]; a1 = afc1[s - 8];
                }
                const int ksb = (s < 4) ? s : (s - 4);
                const uint32_t bS = bAddrQ + ksb * 16 * (LDAB_ * 2);
                #pragma unroll
                for (int n = 0; n < 4; ++n) {
                    uint32_t b0, b1;
                    ldsm_x2t(b0, b1, bS + n * 16);
                    mma_bf16(acc0[n], a0, b0, b1);
                    mma_bf16(acc1[n], a1, b0, b1);
                }
            }

            {
                const int r  = lane >> 2;
                const int cq = (lane & 3) * 2;
                float* s_v2 = (float*)(sm + OFF_V_);
                #pragma unroll
                for (int h = 0; h < 2; ++h) {
                    const int tA = t0g + 32 * sg + 16 * h + r;
                    const float* pmA = pmem + ((size_t)b * T_ + tA) * ATT_;
                    const float* pmB = pmA + 8 * ATT_;
                    float (*ac)[4] = h ? acc1 : acc0;
                    float eA = 0.f, eB = 0.f;
                    #pragma unroll
                    for (int n = 0; n < 4; ++n) {
                        const int col = 32 * nq + 8 * n + cq;
                        float2 v2 = *(const float2*)(s_v2 + col);
                        float2 pa = *(const float2*)(pmA + col);
                        float2 pb = *(const float2*)(pmB + col);
                        eA = fmaf(tanh_fast(ac[n][0] + pa.x), v2.x, eA);
                        eA = fmaf(tanh_fast(ac[n][1] + pa.y), v2.y, eA);
                        eB = fmaf(tanh_fast(ac[n][2] + pb.x), v2.x, eB);
                        eB = fmaf(tanh_fast(ac[n][3] + pb.y), v2.y, eB);
                    }
                    eA += __shfl_xor_sync(0xffffffffu, eA, 1);
                    eA += __shfl_xor_sync(0xffffffffu, eA, 2);
                    eB += __shfl_xor_sync(0xffffffffu, eB, 1);
                    eB += __shfl_xor_sync(0xffffffffu, eB, 2);
                    if ((lane & 3) == 0) {
                        s_e[nq * 1024 + tA]     = eA;
                        s_e[nq * 1024 + tA + 8] = eB;
                    }
                }
            }
            BAR_PROD();
            if (tid == 0) {
                __threadfence_block();
                *s_flag = it + 1;
            }
        }
    } else {
        // ================= CONSUMER (warps 16-19): online softmax-context =================
        const int ct = tid - NPROD_;        // 0..127
        const int cw = ct >> 5, cl = ct & 31;
        float* s_ec   = (float*)(sm + OFF_EC_);
        float* s_p    = (float*)(sm + OFF_P_);
        float* s_cred = (float*)(sm + OFF_CRED_);

        float run_max = NINF, run_sum = 0.f;
        float4 acc = make_float4(0.f, 0.f, 0.f, 0.f);
        const float4* mem4 = (const float4*)memory + (size_t)b * T_ * (EMB_ / 4) + ct;

        for (int it = 0; it < 8; ++it) {
            while (*s_flag < it + 1) __nanosleep(64);
            __threadfence_block();

            const int t = it * 128 + ct;
            float e = (s_e[t] + s_e[1024 + t]) + (s_e[2048 + t] + s_e[3072 + t]);
            if (mask[(size_t)b * T_ + t]) e = NINF;
            s_ec[t] = e;

            float m = e;
            #pragma unroll
            for (int o = 16; o; o >>= 1) m = fmaxf(m, __shfl_xor_sync(0xffffffffu, m, o));
            if (cl == 0) s_cred[cw] = m;
            BAR_CONS();
            const float tm = fmaxf(fmaxf(s_cred[0], s_cred[1]), fmaxf(s_cred[2], s_cred[3]));
            const float Mp = fmaxf(run_max, tm);
            const float scale = (run_max == Mp) ? 1.f : expf(run_max - Mp);

            float p = (e == NINF) ? 0.f : expf(e - Mp);
            s_p[ct] = p;
            float ps = p;
            #pragma unroll
            for (int o = 16; o; o >>= 1) ps += __shfl_xor_sync(0xffffffffu, ps, o);
            if (cl == 0) s_cred[4 + cw] = ps;
            BAR_CONS();
            run_sum = run_sum * scale + ((s_cred[4] + s_cred[5]) + (s_cred[6] + s_cred[7]));
            run_max = Mp;
            acc.x *= scale; acc.y *= scale; acc.z *= scale; acc.w *= scale;

            const float4* mp = mem4 + (size_t)(it * 128) * (EMB_ / 4);
            #pragma unroll 8
            for (int j = 0; j < 128; ++j) {
                float wt = s_p[j];
                float4 mv = __ldcs(mp + (size_t)j * (EMB_ / 4));
                acc.x = fmaf(wt, mv.x, acc.x);
                acc.y = fmaf(wt, mv.y, acc.y);
                acc.z = fmaf(wt, mv.z, acc.z);
                acc.w = fmaf(wt, mv.w, acc.w);
            }
            BAR_CONS();   // done with s_p/s_cred before next tile overwrites
        }

        const float inv = 1.f / run_sum;
        acc.x *= inv; acc.y *= inv; acc.z *= inv; acc.w *= inv;
        ((float4*)out)[(size_t)b * (EMB_ / 4) + ct] = acc;

        float* out_w = out + (size_t)B_ * EMB_;
        #pragma unroll
        for (int i = 0; i < 8; ++i) {
            int idx = ct + 128 * i;
            float e = s_ec[idx];
            out_w[(size_t)b * T_ + idx] = (e == NINF) ? 0.f : expf(e - run_max) * inv;
        }
    }
}

// ============================ launch ============================
extern "C" void kernel_launch(void* const* d_in, const int* in_sizes, int n_in,
                              void* d_out, int out_size) {
    const float* hidden = (const float*)d_in[0];
    const float* memory = (const float*)d_in[1];
    const float* pmem   = (const float*)d_in[2];
    const float* awcat  = (const float*)d_in[3];
    const unsigned char* mask = (const unsigned char*)d_in[4];
    const float* wq     = (const float*)d_in[5];
    const float* wconv  = (const float*)d_in[6];
    const float* wloc   = (const float*)d_in[7];
    const float* vvec   = (const float*)d_in[8];

    float* out = (float*)d_out;

    cudaFuncSetAttribute(fused_kernel,
                         cudaFuncAttributeMaxDynamicSharedMemorySize, ESMEM_);

    fused_kernel<<<B_, NTHR_, ESMEM_>>>(awcat, pmem, vvec, mask,
                                        hidden, wq, wconv, wloc, memory, out);
}